// round 17
// baseline (speedup 1.0000x reference)
#include <cuda_runtime.h>
#include <stdint.h>

#define N_NODES 50000
#define N_EDGES 50000
#define N_PAIRS 800000
#define IN_CH   512
#define HID0    256
#define HID1    128
#define N_TGT   32

// ---------------- scratch (static device globals; no cudaMalloc allowed) ----
__device__ __align__(16) float g_h   [(size_t)N_NODES * HID0];
__device__ __align__(16) float g_fte [(size_t)N_EDGES * HID0];
__device__ __align__(16) float g_hout[(size_t)N_NODES * HID0];
__device__ float g_invDe[N_EDGES], g_invDn[N_NODES];
__device__ int   g_cnt_e[N_EDGES], g_cnt_n[N_NODES];
__device__ int   g_off_e[N_EDGES], g_off_n[N_NODES];
__device__ int   g_cur_e[N_EDGES], g_cur_n[N_NODES];
__device__ int   g_adj_e[N_PAIRS];
__device__ int   g_adj_n[N_PAIRS];
__device__ int   g_bsum[2][64];
__device__ float g_pool[HID1];

// ---------------- threefry2x32 (exact JAX semantics) ------------------------
__host__ __device__ __forceinline__ uint32_t rotl32(uint32_t x, int d) {
    return (x << d) | (x >> (32 - d));
}
__host__ __device__ __forceinline__ void threefry2x32(
    uint32_t k0, uint32_t k1, uint32_t x0, uint32_t x1,
    uint32_t& o0, uint32_t& o1)
{
    uint32_t k2 = k0 ^ k1 ^ 0x1BD11BDAu;
    x0 += k0; x1 += k1;
    x0 += x1; x1 = rotl32(x1,13); x1 ^= x0;
    x0 += x1; x1 = rotl32(x1,15); x1 ^= x0;
    x0 += x1; x1 = rotl32(x1,26); x1 ^= x0;
    x0 += x1; x1 = rotl32(x1, 6); x1 ^= x0;
    x0 += k1; x1 += k2 + 1u;
    x0 += x1; x1 = rotl32(x1,17); x1 ^= x0;
    x0 += x1; x1 = rotl32(x1,29); x1 ^= x0;
    x0 += x1; x1 = rotl32(x1,16); x1 ^= x0;
    x0 += x1; x1 = rotl32(x1,24); x1 ^= x0;
    x0 += k2; x1 += k0 + 2u;
    x0 += x1; x1 = rotl32(x1,13); x1 ^= x0;
    x0 += x1; x1 = rotl32(x1,15); x1 ^= x0;
    x0 += x1; x1 = rotl32(x1,26); x1 ^= x0;
    x0 += x1; x1 = rotl32(x1, 6); x1 ^= x0;
    x0 += k0; x1 += k1 + 3u;
    x0 += x1; x1 = rotl32(x1,17); x1 ^= x0;
    x0 += x1; x1 = rotl32(x1,29); x1 ^= x0;
    x0 += x1; x1 = rotl32(x1,16); x1 ^= x0;
    x0 += x1; x1 = rotl32(x1,24); x1 ^= x0;
    x0 += k1; x1 += k2 + 4u;
    x0 += x1; x1 = rotl32(x1,13); x1 ^= x0;
    x0 += x1; x1 = rotl32(x1,15); x1 ^= x0;
    x0 += x1; x1 = rotl32(x1,26); x1 ^= x0;
    x0 += x1; x1 = rotl32(x1, 6); x1 ^= x0;
    x0 += k2; x1 += k0 + 5u;
    o0 = x0; o1 = x1;
}

// ---------------- small setup kernels ---------------------------------------
__global__ void k_zero() {
    int i = blockIdx.x * blockDim.x + threadIdx.x;
    if (i < N_EDGES) g_cnt_e[i] = 0;
    if (i < N_NODES) g_cnt_n[i] = 0;
    if (i < HID1)    g_pool[i]  = 0.f;
}

__global__ void k_degree(const int* __restrict__ H) {
    int p = blockIdx.x * blockDim.x + threadIdx.x;
    if (p < N_PAIRS) {
        atomicAdd(&g_cnt_n[H[p]], 1);
        atomicAdd(&g_cnt_e[H[N_PAIRS + p]], 1);
    }
}

// ---------------- 3-phase parallel exclusive scan ----------------------------
__global__ void k_scan_part() {
    int arr = blockIdx.y;
    const int* cnt = arr ? g_cnt_n : g_cnt_e;
    int* off       = arr ? g_off_n : g_off_e;
    __shared__ int wsum[32];
    int i = blockIdx.x * 1024 + threadIdx.x;
    int lane = threadIdx.x & 31, w = threadIdx.x >> 5;
    int v = (i < N_EDGES) ? cnt[i] : 0;
    int x = v;
    #pragma unroll
    for (int o = 1; o < 32; o <<= 1) {
        int y = __shfl_up_sync(0xffffffffu, x, o);
        if (lane >= o) x += y;
    }
    if (lane == 31) wsum[w] = x;
    __syncthreads();
    if (w == 0) {
        int s = wsum[lane];
        #pragma unroll
        for (int o = 1; o < 32; o <<= 1) {
            int y = __shfl_up_sync(0xffffffffu, s, o);
            if (lane >= o) s += y;
        }
        wsum[lane] = s;
    }
    __syncthreads();
    int incl = x + ((w > 0) ? wsum[w - 1] : 0);
    if (i < N_EDGES) off[i] = incl - v;
    if (threadIdx.x == 1023) g_bsum[arr][blockIdx.x] = incl;
}

__global__ void k_scan_top() {
    int arr = blockIdx.x;
    __shared__ int s[64];
    int t = threadIdx.x;
    s[t] = (t < 49) ? g_bsum[arr][t] : 0;
    __syncthreads();
    #pragma unroll
    for (int o = 1; o < 64; o <<= 1) {
        int val = (t >= o) ? s[t - o] : 0;
        __syncthreads();
        s[t] += val;
        __syncthreads();
    }
    if (t < 49) g_bsum[arr][t] = s[t];
}

__global__ void k_scan_add() {
    int arr = blockIdx.y;
    int i = blockIdx.x * 1024 + threadIdx.x;
    if (i >= N_EDGES) return;
    int add = blockIdx.x ? g_bsum[arr][blockIdx.x - 1] : 0;
    if (arr == 0) {
        int o = g_off_e[i] + add;
        g_off_e[i] = o; g_cur_e[i] = o;
        g_invDe[i] = 1.0f / fmaxf((float)g_cnt_e[i], 1.0f);
    } else {
        int o = g_off_n[i] + add;
        g_off_n[i] = o; g_cur_n[i] = o;
        g_invDn[i] = 1.0f / fmaxf((float)g_cnt_n[i], 1.0f);
    }
}

__global__ void k_fill(const int* __restrict__ H) {
    int p = blockIdx.x * blockDim.x + threadIdx.x;
    if (p < N_PAIRS) {
        int n = H[p], e = H[N_PAIRS + p];
        g_adj_e[atomicAdd(&g_cur_e[e], 1)] = n;
        g_adj_n[atomicAdd(&g_cur_n[n], 1)] = e;
    }
}

// ---------------- SGEMM: 16x4 tile, row-pair accumulators -------------------
// acc register = {row 2r, row 2r+1} for one column. A pairs come straight from
// the transposed At tile as LDS.128 (no packing MOVs); only the 4 B values
// per kk need {b,b} duplication (4 MOVs vs 16 before) -> fma issue share ~78%.
#define FMA2(d, a, b) asm("fma.rn.f32x2 %0, %1, %2, %0;" : "+l"(d) : "l"(a), "l"(b))
#define BKT 16

__device__ __forceinline__ void cp16(uint32_t dst, const float* src) {
    asm volatile("cp.async.cg.shared.global [%0], [%1], 16;" :: "r"(dst), "l"(src));
}

__global__ void __launch_bounds__(256, 2)
k_gemm(const float* __restrict__ A, const float* __restrict__ B,
       float* __restrict__ C, int M, int N, int K) {
    __shared__ float At[2][BKT][136];    // transposed A: [kk][row]
    __shared__ float Bs[2][BKT][132];
    int tid = threadIdx.x;
    int bm = blockIdx.x * 128;
    int bn = blockIdx.y * 128;
    int warp = tid >> 5, lane = tid & 31;

    int arow = tid >> 1, acol = (tid & 1) << 3;
    int grow = bm + arow; if (grow > M - 1) grow = M - 1;
    const float* Abase = A + (size_t)grow * K + acol;
    int brow = tid >> 4, bcol = (tid & 15) << 3;
    const float* Bbase = B + (size_t)brow * N + bn + bcol;
    uint32_t asB[2];
    asB[0] = (uint32_t)__cvta_generic_to_shared(&Bs[0][brow][bcol]);
    asB[1] = (uint32_t)__cvta_generic_to_shared(&Bs[1][brow][bcol]);

    // acc[p][c] = {row 2p, row 2p+1} x col c   (8 row-pairs x 4 cols)
    unsigned long long acc[8][4];
    #pragma unroll
    for (int p = 0; p < 8; p++)
        #pragma unroll
        for (int c = 0; c < 4; c++) acc[p][c] = 0ull;

    int T = K / BKT;

    float4 av0 = *(const float4*)(Abase);
    float4 av1 = *(const float4*)(Abase + 4);
    cp16(asB[0],      Bbase);
    cp16(asB[0] + 16, Bbase + 4);
    asm volatile("cp.async.commit_group;");
    At[0][acol + 0][arow] = av0.x; At[0][acol + 1][arow] = av0.y;
    At[0][acol + 2][arow] = av0.z; At[0][acol + 3][arow] = av0.w;
    At[0][acol + 4][arow] = av1.x; At[0][acol + 5][arow] = av1.y;
    At[0][acol + 6][arow] = av1.z; At[0][acol + 7][arow] = av1.w;
    asm volatile("cp.async.wait_group 0;");
    __syncthreads();

    for (int t = 0; t < T; t++) {
        int cur = t & 1, nxt = cur ^ 1;
        if (t + 1 < T) {
            av0 = *(const float4*)(Abase + (t + 1) * BKT);
            av1 = *(const float4*)(Abase + (t + 1) * BKT + 4);
            const float* bp = Bbase + (size_t)(t + 1) * BKT * N;
            cp16(asB[nxt],      bp);
            cp16(asB[nxt] + 16, bp + 4);
            asm volatile("cp.async.commit_group;");
        }

        const float* atw = &At[cur][0][warp * 16];
        #pragma unroll
        for (int kk = 0; kk < BKT; kk++) {
            // A row-pairs, loaded directly as packed f32x2 (no MOVs)
            ulonglong2 a01 = *(const ulonglong2*)(atw + kk * 136);       // pairs 0,1
            ulonglong2 a23 = *(const ulonglong2*)(atw + kk * 136 + 4);   // pairs 2,3
            ulonglong2 a45 = *(const ulonglong2*)(atw + kk * 136 + 8);   // pairs 4,5
            ulonglong2 a67 = *(const ulonglong2*)(atw + kk * 136 + 12);  // pairs 6,7
            unsigned long long ap[8] = {a01.x, a01.y, a23.x, a23.y,
                                        a45.x, a45.y, a67.x, a67.y};
            // B: 4 cols, duplicate each into {b,b} (4 MOVs)
            float4 bv = *(const float4*)&Bs[cur][kk][lane * 4];
            unsigned long long b2[4];
            asm("mov.b64 %0, {%1, %1};" : "=l"(b2[0]) : "f"(bv.x));
            asm("mov.b64 %0, {%1, %1};" : "=l"(b2[1]) : "f"(bv.y));
            asm("mov.b64 %0, {%1, %1};" : "=l"(b2[2]) : "f"(bv.z));
            asm("mov.b64 %0, {%1, %1};" : "=l"(b2[3]) : "f"(bv.w));
            #pragma unroll
            for (int p = 0; p < 8; p++) {
                FMA2(acc[p][0], ap[p], b2[0]);
                FMA2(acc[p][1], ap[p], b2[1]);
                FMA2(acc[p][2], ap[p], b2[2]);
                FMA2(acc[p][3], ap[p], b2[3]);
            }
        }

        if (t + 1 < T) {
            At[nxt][acol + 0][arow] = av0.x; At[nxt][acol + 1][arow] = av0.y;
            At[nxt][acol + 2][arow] = av0.z; At[nxt][acol + 3][arow] = av0.w;
            At[nxt][acol + 4][arow] = av1.x; At[nxt][acol + 5][arow] = av1.y;
            At[nxt][acol + 6][arow] = av1.z; At[nxt][acol + 7][arow] = av1.w;
            asm volatile("cp.async.wait_group 0;");
        }
        __syncthreads();
    }

    #pragma unroll
    for (int p = 0; p < 8; p++) {
        float2 c0 = *(float2*)&acc[p][0];   // .x=row even, .y=row odd (col 0)
        float2 c1 = *(float2*)&acc[p][1];
        float2 c2 = *(float2*)&acc[p][2];
        float2 c3 = *(float2*)&acc[p][3];
        int row0 = bm + warp * 16 + 2 * p;
        if (row0 < M)
            *(float4*)(C + (size_t)row0 * N + bn + lane * 4) =
                make_float4(c0.x, c1.x, c2.x, c3.x);
        if (row0 + 1 < M)
            *(float4*)(C + (size_t)(row0 + 1) * N + bn + lane * 4) =
                make_float4(c0.y, c1.y, c2.y, c3.y);
    }
}

// ---------------- sparse gathers (CSR, float4-vectorized) --------------------
template<int C>
__global__ void k_edge_gather(const float* __restrict__ h, float* __restrict__ fte) {
    int e = blockIdx.x;
    int c4 = threadIdx.x;
    int s = g_off_e[e], m = g_cnt_e[e];
    const int* adj = g_adj_e + s;
    const float4* h4 = (const float4*)h;
    float4 acc = make_float4(0.f, 0.f, 0.f, 0.f);
    int j = 0;
    for (; j + 4 <= m; j += 4) {
        int n0 = adj[j], n1 = adj[j + 1], n2 = adj[j + 2], n3 = adj[j + 3];
        float4 a = h4[(size_t)n0 * (C / 4) + c4];
        float4 b = h4[(size_t)n1 * (C / 4) + c4];
        float4 d = h4[(size_t)n2 * (C / 4) + c4];
        float4 f = h4[(size_t)n3 * (C / 4) + c4];
        acc.x += a.x + b.x + d.x + f.x;
        acc.y += a.y + b.y + d.y + f.y;
        acc.z += a.z + b.z + d.z + f.z;
        acc.w += a.w + b.w + d.w + f.w;
    }
    for (; j < m; j++) {
        float4 a = h4[(size_t)adj[j] * (C / 4) + c4];
        acc.x += a.x; acc.y += a.y; acc.z += a.z; acc.w += a.w;
    }
    float inv = g_invDe[e];
    acc.x *= inv; acc.y *= inv; acc.z *= inv; acc.w *= inv;
    ((float4*)fte)[(size_t)e * (C / 4) + c4] = acc;
}

// node aggregation + bias + leaky relu + fused threefry dropout (layer 0)
template<int C>
__global__ void k_node_apply(const float* __restrict__ fte,
                             const float* __restrict__ bias,
                             float* __restrict__ out,
                             uint32_t dk0, uint32_t dk1) {
    int n = blockIdx.x;
    int c4 = threadIdx.x;
    int s = g_off_n[n], m = g_cnt_n[n];
    const int* adj = g_adj_n + s;
    const float4* f4 = (const float4*)fte;
    float4 acc = make_float4(0.f, 0.f, 0.f, 0.f);
    int j = 0;
    for (; j + 4 <= m; j += 4) {
        int e0 = adj[j], e1 = adj[j + 1], e2 = adj[j + 2], e3 = adj[j + 3];
        float4 a = f4[(size_t)e0 * (C / 4) + c4];
        float4 b = f4[(size_t)e1 * (C / 4) + c4];
        float4 d = f4[(size_t)e2 * (C / 4) + c4];
        float4 f = f4[(size_t)e3 * (C / 4) + c4];
        acc.x += a.x + b.x + d.x + f.x;
        acc.y += a.y + b.y + d.y + f.y;
        acc.z += a.z + b.z + d.z + f.z;
        acc.w += a.w + b.w + d.w + f.w;
    }
    for (; j < m; j++) {
        float4 a = f4[(size_t)adj[j] * (C / 4) + c4];
        acc.x += a.x; acc.y += a.y; acc.z += a.z; acc.w += a.w;
    }
    float inv = g_invDn[n];
    float4 bv = ((const float4*)bias)[c4];
    float v[4] = {acc.x * inv + bv.x, acc.y * inv + bv.y,
                  acc.z * inv + bv.z, acc.w * inv + bv.w};
    uint32_t base = (uint32_t)n * C + c4 * 4;
    #pragma unroll
    for (int q = 0; q < 4; q++) {
        float t = v[q];
        t = (t >= 0.f) ? t : 0.01f * t;
        uint32_t o0, o1;
        threefry2x32(dk0, dk1, 0u, base + q, o0, o1);
        v[q] = (((o0 ^ o1) >> 31) == 0u) ? t * 2.0f : 0.0f;
    }
    ((float4*)out)[(size_t)n * (C / 4) + c4] = make_float4(v[0], v[1], v[2], v[3]);
}

// ---- layer-1 node apply FUSED with dropmax + pool (one node per warp) -------
__global__ void k_node_dropmax(const float* __restrict__ fte,
                               const float* __restrict__ bias,
                               float* __restrict__ feats,
                               float* __restrict__ pool,
                               uint32_t dk0, uint32_t dk1) {
    __shared__ float s_pool[HID1];
    int t = threadIdx.x;
    if (t < HID1) s_pool[t] = 0.f;
    __syncthreads();
    int warp = t >> 5, lane = t & 31;
    int n = blockIdx.x * 8 + warp;
    if (n < N_NODES) {
        int s = g_off_n[n], m = g_cnt_n[n];
        const int* adj = g_adj_n + s;
        const float4* f4 = (const float4*)fte;
        float4 acc = make_float4(0.f, 0.f, 0.f, 0.f);
        int j = 0;
        for (; j + 4 <= m; j += 4) {
            int e0 = adj[j], e1 = adj[j + 1], e2 = adj[j + 2], e3 = adj[j + 3];
            float4 a = f4[(size_t)e0 * (HID1 / 4) + lane];
            float4 b = f4[(size_t)e1 * (HID1 / 4) + lane];
            float4 d = f4[(size_t)e2 * (HID1 / 4) + lane];
            float4 f = f4[(size_t)e3 * (HID1 / 4) + lane];
            acc.x += a.x + b.x + d.x + f.x;
            acc.y += a.y + b.y + d.y + f.y;
            acc.z += a.z + b.z + d.z + f.z;
            acc.w += a.w + b.w + d.w + f.w;
        }
        for (; j < m; j++) {
            float4 a = f4[(size_t)adj[j] * (HID1 / 4) + lane];
            acc.x += a.x; acc.y += a.y; acc.z += a.z; acc.w += a.w;
        }
        float inv = g_invDn[n];
        float4 bv = ((const float4*)bias)[lane];
        float v[4] = {acc.x * inv + bv.x, acc.y * inv + bv.y,
                      acc.z * inv + bv.z, acc.w * inv + bv.w};
        uint32_t base = (uint32_t)n * HID1 + lane * 4;
        #pragma unroll
        for (int q = 0; q < 4; q++) {
            float x = v[q];
            x = (x >= 0.f) ? x : 0.01f * x;
            uint32_t o0, o1;
            threefry2x32(dk0, dk1, 0u, base + q, o0, o1);
            v[q] = (((o0 ^ o1) >> 31) == 0u) ? x * 2.0f : 0.0f;
        }
        unsigned long long key[4];
        bool rem[4] = {false, false, false, false};
        #pragma unroll
        for (int q = 0; q < 4; q++) {
            uint32_t b = __float_as_uint(v[q]);
            uint32_t ord = (b & 0x80000000u) ? ~b : (b | 0x80000000u);
            key[q] = ((unsigned long long)ord << 32) |
                     (unsigned long long)(uint32_t)(127 - (lane * 4 + q));
        }
        for (int it = 0; it < 12; it++) {
            unsigned long long best = 0ull;
            #pragma unroll
            for (int q = 0; q < 4; q++) if (!rem[q] && key[q] > best) best = key[q];
            #pragma unroll
            for (int o = 16; o > 0; o >>= 1) {
                unsigned long long other = __shfl_xor_sync(0xffffffffu, best, o);
                if (other > best) best = other;
            }
            #pragma unroll
            for (int q = 0; q < 4; q++) if (key[q] == best) rem[q] = true;
        }
        #pragma unroll
        for (int q = 0; q < 4; q++) if (rem[q]) v[q] = 0.f;
        ((float4*)feats)[(size_t)n * (HID1 / 4) + lane] =
            make_float4(v[0], v[1], v[2], v[3]);
        #pragma unroll
        for (int q = 0; q < 4; q++) atomicAdd(&s_pool[lane * 4 + q], v[q]);
    }
    __syncthreads();
    if (t < HID1) atomicAdd(&pool[t], s_pool[t]);
}

// ---------------- head: mean, fc, sigmoid ------------------------------------
__global__ void k_final(const float* __restrict__ Wfc, const float* __restrict__ bfc,
                        float* __restrict__ d_out) {
    __shared__ float p[HID1];
    int t = threadIdx.x;
    if (t < HID1) {
        float pv = g_pool[t] * (1.0f / (float)N_NODES);
        p[t] = pv;
        d_out[32 + (size_t)N_NODES * HID1 + t] = pv;
    }
    __syncthreads();
    if (t < N_TGT) {
        float acc = bfc[t];
        #pragma unroll 8
        for (int c = 0; c < HID1; c++) acc += p[c] * Wfc[c * N_TGT + t];
        d_out[t] = 1.0f / (1.0f + expf(-acc));
    }
}

// ---------------- launch ------------------------------------------------------
extern "C" void kernel_launch(void* const* d_in, const int* in_sizes, int n_in,
                              void* d_out, int out_size) {
    const float* x   = (const float*)d_in[0];
    const int*   H   = (const int*)  d_in[1];
    const float* W0  = (const float*)d_in[2];
    const float* b0  = (const float*)d_in[3];
    const float* W1  = (const float*)d_in[4];
    const float* b1  = (const float*)d_in[5];
    const float* Wfc = (const float*)d_in[6];
    const float* bfc = (const float*)d_in[7];
    float* out = (float*)d_out;

    float *p_h, *p_fte, *p_hout, *p_pool;
    cudaGetSymbolAddress((void**)&p_h,    g_h);
    cudaGetSymbolAddress((void**)&p_fte,  g_fte);
    cudaGetSymbolAddress((void**)&p_hout, g_hout);
    cudaGetSymbolAddress((void**)&p_pool, g_pool);

    // side stream + fork/join events (created once on first, uncaptured call;
    // reused inside graph capture -> identical DAG every call)
    static cudaStream_t s_b = 0;
    static cudaEvent_t  e_fork = 0, e_join = 0;
    if (!s_b) {
        cudaStreamCreateWithFlags(&s_b, cudaStreamNonBlocking);
        cudaEventCreateWithFlags(&e_fork, cudaEventDisableTiming);
        cudaEventCreateWithFlags(&e_join, cudaEventDisableTiming);
    }

    uint32_t l0k0, l0k1, l1k0, l1k1;
    threefry2x32(0u, 42u, 0u, 0u, l0k0, l0k1);
    threefry2x32(0u, 42u, 0u, 1u, l1k0, l1k1);

    const int NBLK = (N_EDGES + 1023) / 1024;   // 49

    // ---- fork: CSR setup chain on s_b, GEMM0 on main (independent) ---------
    cudaEventRecord(e_fork, 0);
    cudaStreamWaitEvent(s_b, e_fork, 0);

    k_zero     <<<196, 256, 0, s_b>>>();
    k_degree   <<<(N_PAIRS + 255) / 256, 256, 0, s_b>>>(H);
    k_scan_part<<<dim3(NBLK, 2), 1024, 0, s_b>>>();
    k_scan_top <<<2, 64, 0, s_b>>>();
    k_scan_add <<<dim3(NBLK, 2), 1024, 0, s_b>>>();
    k_fill     <<<(N_PAIRS + 255) / 256, 256, 0, s_b>>>(H);

    k_gemm<<<dim3((N_NODES + 127) / 128, HID0 / 128), 256>>>(x, W0, p_h,
                                                             N_NODES, HID0, IN_CH);

    cudaEventRecord(e_join, s_b);
    cudaStreamWaitEvent(0, e_join, 0);

    // ----- layer 0 (rest) -----
    k_edge_gather<HID0><<<N_EDGES, HID0 / 4>>>(p_h, p_fte);
    k_node_apply<HID0><<<N_NODES, HID0 / 4>>>(p_fte, b0, p_hout, l0k0, l0k1);

    // ----- layer 1 -----
    k_gemm<<<dim3((N_NODES + 127) / 128, HID1 / 128), 256>>>(p_hout, W1, p_h,
                                                             N_NODES, HID1, HID0);
    k_edge_gather<HID1><<<N_EDGES, HID1 / 4>>>(p_h, p_fte);

    // ----- fused: node apply + leaky + dropout + dropmax + pool -----
    k_node_dropmax<<<(N_NODES + 7) / 8, 256>>>(p_fte, b1, out + 32, p_pool,
                                               l1k0, l1k1);
    k_final<<<1, 128>>>(Wfc, bfc, out);
}